// round 4
// baseline (speedup 1.0000x reference)
#include <cuda_runtime.h>
#include <cuda_bf16.h>
#include <math.h>

// ---------------- problem constants ----------------
#define BSZ 2
#define TSZ 1024
#define CSZ 768
#define LSZ 12
#define HSZ 12
#define HDSZ 64
#define VSZ 50257
#define BT (BSZ*TSZ)

// ---------------- device scratch (no allocation allowed) ----------------
__device__ float g_x  [BT*CSZ];      // residual stream
__device__ float g_h  [BT*CSZ];      // layernorm output
__device__ float g_qkv[BT*3*CSZ];    // qkv projection
__device__ float g_ao [BT*CSZ];      // attention output (pre-proj)
__device__ float g_hid[BT*4*CSZ];    // MLP hidden

// ---------------- reductions ----------------
__device__ __forceinline__ float warpReduceSum(float v){
    #pragma unroll
    for (int o = 16; o > 0; o >>= 1) v += __shfl_xor_sync(0xffffffffu, v, o);
    return v;
}
__device__ __forceinline__ float warpReduceMax(float v){
    #pragma unroll
    for (int o = 16; o > 0; o >>= 1) v = fmaxf(v, __shfl_xor_sync(0xffffffffu, v, o));
    return v;
}
__device__ __forceinline__ float blockReduceSum(float v, float* sh){
    int lane = threadIdx.x & 31, w = threadIdx.x >> 5;
    v = warpReduceSum(v);
    __syncthreads();
    if (lane == 0) sh[w] = v;
    __syncthreads();
    int nw = blockDim.x >> 5;
    float r = (threadIdx.x < nw) ? sh[threadIdx.x] : 0.0f;
    if (w == 0){ r = warpReduceSum(r); if (lane == 0) sh[0] = r; }
    __syncthreads();
    return sh[0];
}
__device__ __forceinline__ float blockReduceMax(float v, float* sh){
    int lane = threadIdx.x & 31, w = threadIdx.x >> 5;
    v = warpReduceMax(v);
    __syncthreads();
    if (lane == 0) sh[w] = v;
    __syncthreads();
    int nw = blockDim.x >> 5;
    float r = (threadIdx.x < nw) ? sh[threadIdx.x] : -1e30f;
    if (w == 0){ r = warpReduceMax(r); if (lane == 0) sh[0] = r; }
    __syncthreads();
    return sh[0];
}

// ---------------- embedding ----------------
__global__ void embed_kernel(const int* __restrict__ idx,
                             const float* __restrict__ wte,
                             const float* __restrict__ wpe,
                             float* __restrict__ x){
    int i = blockIdx.x * blockDim.x + threadIdx.x;
    if (i >= BT*CSZ) return;
    int c  = i % CSZ;
    int bt = i / CSZ;
    int t  = bt % TSZ;
    x[i] = wte[(size_t)idx[bt]*CSZ + c] + wpe[(size_t)t*CSZ + c];
}

// ---------------- layernorm (one block per row, C=768, 256 thr x 3) ----------------
__global__ void __launch_bounds__(256) ln_kernel(const float* __restrict__ x,
                                                 const float* __restrict__ g,
                                                 const float* __restrict__ b,
                                                 float* __restrict__ out){
    __shared__ float sh[32];
    int row = blockIdx.x, tid = threadIdx.x;
    const float* xr = x + (size_t)row*CSZ;
    float v0 = xr[tid], v1 = xr[tid+256], v2 = xr[tid+512];
    float mean = blockReduceSum(v0+v1+v2, sh) * (1.0f/CSZ);
    float d0 = v0-mean, d1 = v1-mean, d2 = v2-mean;
    float var = blockReduceSum(d0*d0 + d1*d1 + d2*d2, sh) * (1.0f/CSZ);
    float rs = rsqrtf(var + 1e-5f);
    float* orow = out + (size_t)row*CSZ;
    orow[tid    ] = d0*rs*g[tid    ] + b[tid    ];
    orow[tid+256] = d1*rs*g[tid+256] + b[tid+256];
    orow[tid+512] = d2*rs*g[tid+512] + b[tid+512];
}

// ---------------- SGEMM 128x128x16, 8x8 per thread ----------------
// C[M,N] = A[M,K] @ B  (+bias +residual, optional exact GELU)
// transB=0: B is [K,N] row-major.  transB=1: B is [N,K] row-major (logits head).
// Assumes: M multiple of 128, K multiple of 16, A rows 16B-aligned.
// N guarded (logits N=50257); for transB==0 callers N is a multiple of 128.
#define BM 128
#define BN 128
#define BK 16

__global__ void __launch_bounds__(256) gemm_kernel(
    const float* __restrict__ A, const float* __restrict__ B,
    const float* __restrict__ bias, const float* __restrict__ res,
    float* __restrict__ Cmat, int M, int N, int K, int transB, int doGelu)
{
    __shared__ float As[BK][BM];
    __shared__ float Bs[BK][BN];

    int tid = threadIdx.x;
    int bm = blockIdx.y * BM, bn = blockIdx.x * BN;
    int tx = tid & 15, ty = tid >> 4;

    float acc[8][8];
    #pragma unroll
    for (int i = 0; i < 8; i++)
        #pragma unroll
        for (int j = 0; j < 8; j++) acc[i][j] = 0.0f;

    int arow = tid >> 1, akc = (tid & 1) << 3;       // A: 128 rows x 16 cols
    const float* aptr = A + (size_t)(bm + arow)*K + akc;

    for (int k0 = 0; k0 < K; k0 += BK){
        // --- load A tile (transposed into As[k][m]) ---
        {
            float4 a0 = *(const float4*)(aptr + k0);
            float4 a1 = *(const float4*)(aptr + k0 + 4);
            As[akc+0][arow]=a0.x; As[akc+1][arow]=a0.y; As[akc+2][arow]=a0.z; As[akc+3][arow]=a0.w;
            As[akc+4][arow]=a1.x; As[akc+5][arow]=a1.y; As[akc+6][arow]=a1.z; As[akc+7][arow]=a1.w;
        }
        // --- load B tile ---
        if (!transB){
            int r = tid >> 5, c = (tid & 31) << 2;   // 8 rows/pass x 128 cols
            const float* bp = B + (size_t)(k0 + r)*N + bn + c;
            float4 b0 = *(const float4*)bp;
            float4 b1 = *(const float4*)(bp + (size_t)8*N);
            Bs[r  ][c]=b0.x; Bs[r  ][c+1]=b0.y; Bs[r  ][c+2]=b0.z; Bs[r  ][c+3]=b0.w;
            Bs[r+8][c]=b1.x; Bs[r+8][c+1]=b1.y; Bs[r+8][c+2]=b1.z; Bs[r+8][c+3]=b1.w;
        } else {
            int n = tid >> 1, kc = (tid & 1) << 3;   // B[N,K]: 128 n-rows x 16 k
            int gn = bn + n;
            float4 b0 = make_float4(0,0,0,0), b1 = make_float4(0,0,0,0);
            if (gn < N){
                const float* bp = B + (size_t)gn*K + k0 + kc;
                b0 = *(const float4*)bp;
                b1 = *(const float4*)(bp + 4);
            }
            Bs[kc+0][n]=b0.x; Bs[kc+1][n]=b0.y; Bs[kc+2][n]=b0.z; Bs[kc+3][n]=b0.w;
            Bs[kc+4][n]=b1.x; Bs[kc+5][n]=b1.y; Bs[kc+6][n]=b1.z; Bs[kc+7][n]=b1.w;
        }
        __syncthreads();

        #pragma unroll
        for (int kk = 0; kk < BK; kk++){
            float4 a0 = *(const float4*)&As[kk][ty*8];
            float4 a1 = *(const float4*)&As[kk][ty*8+4];
            float4 b0 = *(const float4*)&Bs[kk][tx*8];
            float4 b1 = *(const float4*)&Bs[kk][tx*8+4];
            float av[8] = {a0.x,a0.y,a0.z,a0.w,a1.x,a1.y,a1.z,a1.w};
            float bv[8] = {b0.x,b0.y,b0.z,b0.w,b1.x,b1.y,b1.z,b1.w};
            #pragma unroll
            for (int i = 0; i < 8; i++)
                #pragma unroll
                for (int j = 0; j < 8; j++)
                    acc[i][j] = fmaf(av[i], bv[j], acc[i][j]);
        }
        __syncthreads();
    }

    // --- epilogue ---
    #pragma unroll
    for (int i = 0; i < 8; i++){
        int gm = bm + ty*8 + i;
        #pragma unroll
        for (int j = 0; j < 8; j++){
            int gn = bn + tx*8 + j;
            if (gn < N){
                float v = acc[i][j];
                if (bias) v += bias[gn];
                if (res)  v += res[(size_t)gm*N + gn];
                if (doGelu) v = 0.5f*v*(1.0f + erff(v*0.70710678118654752f));
                Cmat[(size_t)gm*N + gn] = v;
            }
        }
    }
}

// ---------------- fused causal attention: one block per (b,h,t) ----------------
// qkv layout per reference reshape(B,T,H,3*HD): for head h, within the 2304-wide
// row, q = [h*192, +64), k = [h*192+64, +64), v = [h*192+128, +64).
__global__ void __launch_bounds__(128) attn_kernel(const float* __restrict__ qkv,
                                                   float* __restrict__ out){
    int t = blockIdx.x, h = blockIdx.y, b = blockIdx.z;
    __shared__ float q[HDSZ];
    __shared__ float p[TSZ];
    __shared__ float sh[32];
    int tid = threadIdx.x;

    const float* base = qkv + (size_t)b*TSZ*3*CSZ;
    const float* qr = base + (size_t)t*3*CSZ + h*3*HDSZ;
    if (tid < HDSZ) q[tid] = qr[tid] * 0.125f;   // 1/sqrt(64), folded into q
    __syncthreads();

    float mymax = -1e30f;
    for (int s = tid; s <= t; s += 128){
        const float* kr = base + (size_t)s*3*CSZ + h*3*HDSZ + HDSZ;
        float d = 0.0f;
        #pragma unroll
        for (int i = 0; i < HDSZ; i++) d = fmaf(q[i], kr[i], d);
        p[s] = d;
        mymax = fmaxf(mymax, d);
    }
    float mx = blockReduceMax(mymax, sh);

    float mysum = 0.0f;
    for (int s = tid; s <= t; s += 128){
        float e = __expf(p[s] - mx);
        p[s] = e;
        mysum += e;
    }
    float inv = 1.0f / blockReduceSum(mysum, sh);   // includes __syncthreads

    if (tid < HDSZ){
        float acc = 0.0f;
        const float* vr = base + h*3*HDSZ + 2*HDSZ + tid;
        for (int s = 0; s <= t; s++)
            acc = fmaf(p[s], vr[(size_t)s*3*CSZ], acc);
        out[((size_t)(b*TSZ + t))*CSZ + h*HDSZ + tid] = acc * inv;
    }
}

// ---------------- launch ----------------
extern "C" void kernel_launch(void* const* d_in, const int* in_sizes, int n_in,
                              void* d_out, int out_size)
{
    const int*   idx    = (const int*)  d_in[0];
    const float* wte    = (const float*)d_in[1];
    const float* wpe    = (const float*)d_in[2];
    const float* ln1_g  = (const float*)d_in[3];
    const float* ln1_b  = (const float*)d_in[4];
    const float* attn_w = (const float*)d_in[5];
    const float* attn_b = (const float*)d_in[6];
    const float* proj_w = (const float*)d_in[7];
    const float* proj_b = (const float*)d_in[8];
    const float* ln2_g  = (const float*)d_in[9];
    const float* ln2_b  = (const float*)d_in[10];
    const float* fc_w   = (const float*)d_in[11];
    const float* fc_b   = (const float*)d_in[12];
    const float* fp_w   = (const float*)d_in[13];
    const float* fp_b   = (const float*)d_in[14];
    const float* lnf_g  = (const float*)d_in[15];
    const float* lnf_b  = (const float*)d_in[16];
    float* out = (float*)d_out;

    float *x, *h, *qkv, *ao, *hid;
    cudaGetSymbolAddress((void**)&x,   g_x);
    cudaGetSymbolAddress((void**)&h,   g_h);
    cudaGetSymbolAddress((void**)&qkv, g_qkv);
    cudaGetSymbolAddress((void**)&ao,  g_ao);
    cudaGetSymbolAddress((void**)&hid, g_hid);

    embed_kernel<<<(BT*CSZ + 255)/256, 256>>>(idx, wte, wpe, x);

    for (int l = 0; l < LSZ; l++){
        // attention
        ln_kernel<<<BT, 256>>>(x, ln1_g + (size_t)l*CSZ, ln1_b + (size_t)l*CSZ, h);
        gemm_kernel<<<dim3(3*CSZ/BN, BT/BM), 256>>>(
            h, attn_w + (size_t)l*CSZ*3*CSZ, attn_b + (size_t)l*3*CSZ,
            nullptr, qkv, BT, 3*CSZ, CSZ, 0, 0);
        attn_kernel<<<dim3(TSZ, HSZ, BSZ), 128>>>(qkv, ao);
        gemm_kernel<<<dim3(CSZ/BN, BT/BM), 256>>>(
            ao, proj_w + (size_t)l*CSZ*CSZ, proj_b + (size_t)l*CSZ,
            x, x, BT, CSZ, CSZ, 0, 0);
        // MLP
        ln_kernel<<<BT, 256>>>(x, ln2_g + (size_t)l*CSZ, ln2_b + (size_t)l*CSZ, h);
        gemm_kernel<<<dim3(4*CSZ/BN, BT/BM), 256>>>(
            h, fc_w + (size_t)l*CSZ*4*CSZ, fc_b + (size_t)l*4*CSZ,
            nullptr, hid, BT, 4*CSZ, CSZ, 0, 1);
        gemm_kernel<<<dim3(CSZ/BN, BT/BM), 256>>>(
            hid, fp_w + (size_t)l*4*CSZ*CSZ, fp_b + (size_t)l*CSZ,
            x, x, BT, CSZ, 4*CSZ, 0, 0);
    }

    // final LN + tied-embedding logits head (B transposed: wte is [V, C])
    ln_kernel<<<BT, 256>>>(x, lnf_g, lnf_b, h);
    gemm_kernel<<<dim3((VSZ + BN - 1)/BN, BT/BM), 256>>>(
        h, wte, nullptr, nullptr, out, BT, VSZ, CSZ, 1, 0);
}